// round 1
// baseline (speedup 1.0000x reference)
#include <cuda_runtime.h>
#include <cstdint>

#define BS      128
#define NQ      900
#define NC      91
#define NTOT    (NQ * NC)     /* 81900 */
#define MSEL    1024          /* guaranteed-selected top count */
#define SORT_N  2048          /* bitonic sort size (>= collected count) */
#define NPRE    512           /* candidates with precomputed boxes */
#define NPOST   100
#define NBINS   4096
#define NTHREADS 1024
#define IOU_THR 0.7f

// ---- XLA logistic replica: 0.5 + 0.5 * fast_tanh(0.5 * x), non-fused ----
__device__ __forceinline__ float xla_logistic(float x) {
    float t_in = __fmul_rn(x, 0.5f);
    float ax = fabsf(t_in);
    float t;
    if (ax < 0.0004f) {
        t = t_in;
    } else {
        float xc = fminf(fmaxf(t_in, -9.0f), 9.0f);
        float x2 = __fmul_rn(xc, xc);
        float p = -2.76076847742355e-16f;                       // alpha_13
        p = __fadd_rn(__fmul_rn(p, x2), 2.00018790482477e-13f); // alpha_11
        p = __fadd_rn(__fmul_rn(p, x2), -8.60467152213735e-11f);// alpha_9
        p = __fadd_rn(__fmul_rn(p, x2), 5.12229709037114e-08f); // alpha_7
        p = __fadd_rn(__fmul_rn(p, x2), 1.48572235717979e-05f); // alpha_5
        p = __fadd_rn(__fmul_rn(p, x2), 6.37261928875436e-04f); // alpha_3
        p = __fadd_rn(__fmul_rn(p, x2), 4.89352455891786e-03f); // alpha_1
        p = __fmul_rn(p, xc);
        float q = 1.19825839466702e-06f;                        // beta_6
        q = __fadd_rn(__fmul_rn(q, x2), 1.18534705686654e-04f); // beta_4
        q = __fadd_rn(__fmul_rn(q, x2), 2.26843463243900e-03f); // beta_2
        q = __fadd_rn(__fmul_rn(q, x2), 4.89352518554385e-03f); // beta_0
        t = __fdiv_rn(p, q);
    }
    return __fadd_rn(0.5f, __fmul_rn(0.5f, t));
}

__device__ __forceinline__ unsigned int ordered_bits(float x) {
    unsigned int u = __float_as_uint(x);
    return (u & 0x80000000u) ? ~u : (u | 0x80000000u);
}

__global__ __launch_bounds__(NTHREADS, 1)
void nms_post_kernel(const float* __restrict__ logits,
                     const float* __restrict__ boxes,
                     const float* __restrict__ tsz,
                     float* __restrict__ out) {
    __shared__ unsigned long long s_keys[SORT_N];        // 16KB; aliased as hist
    __shared__ unsigned int s_coarse[NTHREADS];          // 4KB
    __shared__ float s_bx1[NPRE], s_by1[NPRE], s_bx2[NPRE], s_by2[NPRE];
    __shared__ int   s_lab[NPRE];
    __shared__ float s_px1[NPOST], s_py1[NPOST], s_px2[NPOST], s_py2[NPOST], s_par[NPOST];
    __shared__ int   s_plab[NPOST];
    __shared__ int   s_pkj[NPOST];
    __shared__ int   s_cnt, s_bin, s_g;

    const int img = blockIdx.x;
    const int tid = threadIdx.x;
    unsigned int* hist = reinterpret_cast<unsigned int*>(s_keys); // 4096 bins == 16KB

    const float* lg = logits + (size_t)img * NTOT;
    const float* bx = boxes + (size_t)img * NQ * 4;
    const float img_h = tsz[img * 2 + 0];
    const float img_w = tsz[img * 2 + 1];

    // ---- Phase 1: histogram of logit ordered-bits (top 12 bits) ----
    for (int i = tid; i < NBINS; i += NTHREADS) hist[i] = 0u;
    __syncthreads();
    for (int i = tid; i < NTOT; i += NTHREADS) {
        unsigned int ou = ordered_bits(lg[i]);
        atomicAdd(&hist[ou >> 20], 1u);
    }
    __syncthreads();

    // ---- Phase 2: find threshold bin b such that count(bin >= b) >= MSEL ----
    {
        int b4 = tid * 4;
        s_coarse[tid] = hist[b4] + hist[b4 + 1] + hist[b4 + 2] + hist[b4 + 3];
    }
    __syncthreads();
    for (int off = 1; off < NTHREADS; off <<= 1) {   // inclusive suffix scan
        unsigned int v = (tid + off < NTHREADS) ? s_coarse[tid + off] : 0u;
        __syncthreads();
        s_coarse[tid] += v;
        __syncthreads();
    }
    {
        unsigned int mine = s_coarse[tid];
        unsigned int nxt = (tid < NTHREADS - 1) ? s_coarse[tid + 1] : 0u;
        if (mine >= MSEL && nxt < MSEL) s_g = tid;   // unique crossing
    }
    __syncthreads();
    if (tid == 0) {
        int g = s_g;
        unsigned int cum = (g < NTHREADS - 1) ? s_coarse[g + 1] : 0u;
        int b = g * 4;
        for (int bin = g * 4 + 3; bin >= g * 4; --bin) {
            cum += hist[bin];
            if (cum >= MSEL) { b = bin; break; }
        }
        s_bin = b;
        s_cnt = 0;
    }
    __syncthreads();
    const int bthr = s_bin;

    // ---- Phase 3: zero key buffer (kills hist), collect candidates ----
    for (int i = tid; i < SORT_N; i += NTHREADS) s_keys[i] = 0ull;
    __syncthreads();
    for (int i = tid; i < NTOT; i += NTHREADS) {
        float x = lg[i];
        unsigned int ou = ordered_bits(x);
        if ((int)(ou >> 20) >= bthr) {
            float p = xla_logistic(x);
            int pos = atomicAdd(&s_cnt, 1);
            if (pos < SORT_N) {
                s_keys[pos] = ((unsigned long long)__float_as_uint(p) << 32)
                            | (unsigned int)(~(unsigned int)i);
            }
        }
    }
    __syncthreads();
    const int cnt = (s_cnt < SORT_N) ? s_cnt : SORT_N;

    // ---- Phase 4: bitonic sort descending (prob desc, idx asc) ----
    for (int k = 2; k <= SORT_N; k <<= 1) {
        for (int j = k >> 1; j > 0; j >>= 1) {
            for (int idx = tid; idx < SORT_N; idx += NTHREADS) {
                int l = idx ^ j;
                if (l > idx) {
                    unsigned long long a = s_keys[idx];
                    unsigned long long b = s_keys[l];
                    bool desc = ((idx & k) == 0);
                    if (desc ? (a < b) : (a > b)) {
                        s_keys[idx] = b;
                        s_keys[l] = a;
                    }
                }
            }
            __syncthreads();
        }
    }

    // ---- Phase 5: precompute boxes (xyxy, scaled) for first NPRE candidates ----
    for (int j = tid; j < NPRE; j += NTHREADS) {
        if (j < cnt) {
            unsigned long long key = s_keys[j];
            int idx = (int)(~(unsigned int)key);
            int q = idx / NC, lbl = idx - q * NC;
            float cx = bx[q * 4 + 0], cy = bx[q * 4 + 1];
            float w  = bx[q * 4 + 2], h  = bx[q * 4 + 3];
            s_bx1[j] = (cx - 0.5f * w) * img_w;
            s_by1[j] = (cy - 0.5f * h) * img_h;
            s_bx2[j] = (cx + 0.5f * w) * img_w;
            s_by2[j] = (cy + 0.5f * h) * img_h;
            s_lab[j] = lbl;
        } else {
            s_lab[j] = -1;
        }
    }
    __syncthreads();

    // ---- Phase 6: sequential greedy NMS (warp 0, class-aware) ----
    if (tid < 32) {
        const int lane = tid;
        int npick = 0;
        for (int j = 0; j < cnt && npick < NPOST; ++j) {
            float x1, y1, x2, y2; int lbl;
            if (j < NPRE) {
                x1 = s_bx1[j]; y1 = s_by1[j]; x2 = s_bx2[j]; y2 = s_by2[j]; lbl = s_lab[j];
            } else { // cold fallback (effectively unreachable)
                unsigned long long key = s_keys[j];
                int idx = (int)(~(unsigned int)key);
                int q = idx / NC; lbl = idx - q * NC;
                float cx = bx[q * 4 + 0], cy = bx[q * 4 + 1];
                float w  = bx[q * 4 + 2], h  = bx[q * 4 + 3];
                x1 = (cx - 0.5f * w) * img_w; y1 = (cy - 0.5f * h) * img_h;
                x2 = (cx + 0.5f * w) * img_w; y2 = (cy + 0.5f * h) * img_h;
            }
            float aj = (x2 - x1) * (y2 - y1);
            bool sup = false;
            for (int p = lane; p < npick; p += 32) {
                if (s_plab[p] == lbl) {
                    float xx1 = fmaxf(s_px1[p], x1);
                    float yy1 = fmaxf(s_py1[p], y1);
                    float xx2 = fminf(s_px2[p], x2);
                    float yy2 = fminf(s_py2[p], y2);
                    float inter = fmaxf(xx2 - xx1, 0.0f) * fmaxf(yy2 - yy1, 0.0f);
                    float uni = s_par[p] + aj - inter;
                    float iou = inter / fmaxf(uni, 1e-9f);
                    sup |= (iou > IOU_THR);
                }
            }
            if (!__any_sync(0xffffffffu, sup)) {
                if (lane == 0) {
                    s_px1[npick] = x1; s_py1[npick] = y1;
                    s_px2[npick] = x2; s_py2[npick] = y2;
                    s_par[npick] = aj; s_plab[npick] = lbl; s_pkj[npick] = j;
                }
                __syncwarp();
                npick++;
            }
        }
        if (lane == 0) {
            for (; npick < NPOST; ++npick) s_pkj[npick] = 0; // reference argmax-of-all--inf = 0
        }
    }
    __syncthreads();

    // ---- Phase 7: outputs: [scores 128*100 | labels 128*100 | boxes 128*100*4] f32 ----
    for (int k = tid; k < NPOST; k += NTHREADS) {
        int j = s_pkj[k];
        unsigned long long key = s_keys[j];
        float score = __uint_as_float((unsigned int)(key >> 32));
        int idx = (int)(~(unsigned int)key);
        int q = idx / NC, lbl = idx - q * NC;
        float cx = bx[q * 4 + 0], cy = bx[q * 4 + 1];
        float w  = bx[q * 4 + 2], h  = bx[q * 4 + 3];
        float x1 = (cx - 0.5f * w) * img_w;
        float y1 = (cy - 0.5f * h) * img_h;
        float x2 = (cx + 0.5f * w) * img_w;
        float y2 = (cy + 0.5f * h) * img_h;

        out[(size_t)img * NPOST + k] = score;
        out[(size_t)BS * NPOST + (size_t)img * NPOST + k] = (float)lbl;
        float* ob = out + (size_t)2 * BS * NPOST + ((size_t)img * NPOST + k) * 4;
        ob[0] = x1; ob[1] = y1; ob[2] = x2; ob[3] = y2;
    }
}

extern "C" void kernel_launch(void* const* d_in, const int* in_sizes, int n_in,
                              void* d_out, int out_size) {
    const float* pred_logits  = (const float*)d_in[0]; // [128,900,91]
    const float* pred_boxes   = (const float*)d_in[1]; // [128,900,4]
    const float* target_sizes = (const float*)d_in[2]; // [128,2]
    float* out = (float*)d_out;                        // 76800 f32
    (void)in_sizes; (void)n_in; (void)out_size;
    nms_post_kernel<<<BS, NTHREADS>>>(pred_logits, pred_boxes, target_sizes, out);
}

// round 2
// speedup vs baseline: 1.3441x; 1.3441x over previous
#include <cuda_runtime.h>
#include <cstdint>

#define BS      128
#define NQ      900
#define NC      91
#define NTOT    (NQ * NC)     /* 81900 */
#define NVEC    (NTOT / 4)    /* 20475 */
#define TSEL    256           /* threads-above-threshold target */
#define SORT_N  1024
#define NPRE    512
#define NPOST   100
#define NBINS   8192          /* 13-bit ordered-float bins */
#define NTHREADS 1024
#define IOU_THR 0.7f

// ---- XLA logistic replica: 0.5 + 0.5 * fast_tanh(0.5 * x), non-fused ----
__device__ __forceinline__ float xla_logistic(float x) {
    float t_in = __fmul_rn(x, 0.5f);
    float ax = fabsf(t_in);
    float t;
    if (ax < 0.0004f) {
        t = t_in;
    } else {
        float xc = fminf(fmaxf(t_in, -9.0f), 9.0f);
        float x2 = __fmul_rn(xc, xc);
        float p = -2.76076847742355e-16f;
        p = __fadd_rn(__fmul_rn(p, x2), 2.00018790482477e-13f);
        p = __fadd_rn(__fmul_rn(p, x2), -8.60467152213735e-11f);
        p = __fadd_rn(__fmul_rn(p, x2), 5.12229709037114e-08f);
        p = __fadd_rn(__fmul_rn(p, x2), 1.48572235717979e-05f);
        p = __fadd_rn(__fmul_rn(p, x2), 6.37261928875436e-04f);
        p = __fadd_rn(__fmul_rn(p, x2), 4.89352455891786e-03f);
        p = __fmul_rn(p, xc);
        float q = 1.19825839466702e-06f;
        q = __fadd_rn(__fmul_rn(q, x2), 1.18534705686654e-04f);
        q = __fadd_rn(__fmul_rn(q, x2), 2.26843463243900e-03f);
        q = __fadd_rn(__fmul_rn(q, x2), 4.89352518554385e-03f);
        t = __fdiv_rn(p, q);
    }
    return __fadd_rn(0.5f, __fmul_rn(0.5f, t));
}

__device__ __forceinline__ unsigned int ordered_bits(float x) {
    unsigned int u = __float_as_uint(x);
    int s = ((int)u) >> 31;                 // 0 or -1
    return u ^ ((unsigned int)s | 0x80000000u);
}

__device__ __forceinline__ unsigned int inv_ordered(unsigned int ob) {
    return (ob & 0x80000000u) ? (ob ^ 0x80000000u) : ~ob;
}

struct __align__(16) ShKeysBoxes {
    unsigned long long keys[SORT_N];   // 8 KB
    float4 cbox[NPRE];                 // 8 KB
    int    clab[NPRE];                 // 2 KB
};

__global__ __launch_bounds__(NTHREADS, 1)
void nms_post_kernel(const float* __restrict__ logits,
                     const float* __restrict__ boxes,
                     const float* __restrict__ tsz,
                     float* __restrict__ out) {
    __shared__ union {
        unsigned int hist[NBINS];      // 32 KB (phase 2 only)
        ShKeysBoxes  s;                // 18 KB (phases 3+)
    } U;
    __shared__ unsigned int s_coarse[NTHREADS];  // 4 KB
    __shared__ float4 s_pbox[NPOST];
    __shared__ float  s_par[NPOST];
    __shared__ int    s_plab[NPOST];
    __shared__ int    s_pkj[NPOST];
    __shared__ int    s_cnt, s_bin, s_g;

    const int img = blockIdx.x;
    const int tid = threadIdx.x;

    const float*  lg  = logits + (size_t)img * NTOT;
    const float4* lg4 = reinterpret_cast<const float4*>(lg);
    const float*  bxp = boxes + (size_t)img * NQ * 4;
    const float4* bx4 = reinterpret_cast<const float4*>(bxp);
    const float img_h = tsz[img * 2 + 0];
    const float img_w = tsz[img * 2 + 1];

    // ---- Phase 1: single read pass; per-thread top-4 keys in registers ----
    // key = ordered(logit)<<32 | ~idx  (desc logit, asc idx)
    unsigned long long k0 = 0, k1 = 0, k2 = 0, k3 = 0;
    unsigned int k3h = 0;
    for (int i = tid; i < NVEC; i += NTHREADS) {
        float4 v = lg4[i];
        float vv[4] = {v.x, v.y, v.z, v.w};
        const int base = i * 4;
        #pragma unroll
        for (int c = 0; c < 4; ++c) {
            unsigned int ob = ordered_bits(vv[c]);
            if (ob >= k3h) {
                unsigned long long key =
                    ((unsigned long long)ob << 32) | (unsigned int)(~(base + c));
                if (key > k3) {
                    if (key > k1) {
                        if (key > k0) { k3 = k2; k2 = k1; k1 = k0; k0 = key; }
                        else          { k3 = k2; k2 = k1; k1 = key; }
                    } else {
                        if (key > k2) { k3 = k2; k2 = key; }
                        else          { k3 = key; }
                    }
                    k3h = (unsigned int)(k3 >> 32);
                }
            }
        }
    }

    // ---- Phase 2: histogram of per-thread MAX (1024 atomics) -> threshold ----
    for (int i = tid; i < NBINS; i += NTHREADS) U.hist[i] = 0u;
    __syncthreads();
    atomicAdd(&U.hist[(unsigned int)(k0 >> 32) >> 19], 1u);
    __syncthreads();
    {
        int b8 = tid * 8;
        unsigned int sum = 0;
        #pragma unroll
        for (int c = 0; c < 8; ++c) sum += U.hist[b8 + c];
        s_coarse[tid] = sum;
    }
    __syncthreads();
    for (int off = 1; off < NTHREADS; off <<= 1) {   // inclusive suffix scan
        unsigned int v = (tid + off < NTHREADS) ? s_coarse[tid + off] : 0u;
        __syncthreads();
        s_coarse[tid] += v;
        __syncthreads();
    }
    {
        unsigned int mine = s_coarse[tid];
        unsigned int nxt = (tid < NTHREADS - 1) ? s_coarse[tid + 1] : 0u;
        if (mine >= TSEL && nxt < TSEL) s_g = tid;   // unique crossing (total=1024>=TSEL)
    }
    __syncthreads();
    if (tid == 0) {
        int g = s_g;
        unsigned int cum = (g < NTHREADS - 1) ? s_coarse[g + 1] : 0u;
        int b = g * 8;
        for (int bin = g * 8 + 7; bin >= g * 8; --bin) {
            cum += U.hist[bin];
            if (cum >= TSEL) { b = bin; break; }
        }
        s_bin = b;
        s_cnt = 0;
    }
    __syncthreads();
    const unsigned int bthr = (unsigned int)s_bin;
    __syncthreads();   // everyone done reading hist before keys overwrite it

    // ---- Phase 3: collect register candidates above threshold bin ----
    for (int i = tid; i < SORT_N; i += NTHREADS) U.s.keys[i] = 0ull;
    __syncthreads();
    {
        unsigned long long cand[4] = {k0, k1, k2, k3};
        #pragma unroll
        for (int c = 0; c < 4; ++c) {
            unsigned int ob = (unsigned int)(cand[c] >> 32);
            if ((ob >> 19) >= bthr) {
                float x = __uint_as_float(inv_ordered(ob));
                float p = xla_logistic(x);
                int pos = atomicAdd(&s_cnt, 1);
                if (pos < SORT_N) {
                    U.s.keys[pos] = ((unsigned long long)__float_as_uint(p) << 32)
                                  | (unsigned int)(cand[c]);   // low 32 = ~idx
                }
            }
        }
    }
    __syncthreads();
    const int cnt = (s_cnt < SORT_N) ? s_cnt : SORT_N;

    // ---- Phase 4: bitonic sort 1024 keys descending (prob desc, idx asc) ----
    for (int k = 2; k <= SORT_N; k <<= 1) {
        for (int j = k >> 1; j > 0; j >>= 1) {
            int l = tid ^ j;
            if (l > tid) {
                unsigned long long a = U.s.keys[tid];
                unsigned long long b = U.s.keys[l];
                bool desc = ((tid & k) == 0);
                if (desc ? (a < b) : (a > b)) {
                    U.s.keys[tid] = b;
                    U.s.keys[l] = a;
                }
            }
            __syncthreads();
        }
    }

    // ---- Phase 5: precompute scaled xyxy boxes for first NPRE candidates ----
    if (tid < NPRE) {
        const int j = tid;
        if (j < cnt) {
            unsigned long long key = U.s.keys[j];
            int idx = (int)(~(unsigned int)key);
            int q = idx / NC, lbl = idx - q * NC;
            float4 b = bx4[q];                       // cx, cy, w, h
            float x1 = (b.x - 0.5f * b.z) * img_w;
            float y1 = (b.y - 0.5f * b.w) * img_h;
            float x2 = (b.x + 0.5f * b.z) * img_w;
            float y2 = (b.y + 0.5f * b.w) * img_h;
            U.s.cbox[j] = make_float4(x1, y1, x2, y2);
            U.s.clab[j] = lbl;
        } else {
            U.s.clab[j] = -1;
        }
    }
    __syncthreads();

    // ---- Phase 6: sequential greedy class-aware NMS (warp 0) ----
    if (tid < 32) {
        const int lane = tid;
        int npick = 0;
        for (int j = 0; j < cnt && npick < NPOST; ++j) {
            float4 cb; int lbl;
            if (j < NPRE) {
                cb = U.s.cbox[j]; lbl = U.s.clab[j];
            } else {  // cold fallback
                unsigned long long key = U.s.keys[j];
                int idx = (int)(~(unsigned int)key);
                int q = idx / NC; lbl = idx - q * NC;
                float4 b = bx4[q];
                cb.x = (b.x - 0.5f * b.z) * img_w;
                cb.y = (b.y - 0.5f * b.w) * img_h;
                cb.z = (b.x + 0.5f * b.z) * img_w;
                cb.w = (b.y + 0.5f * b.w) * img_h;
            }
            float aj = (cb.z - cb.x) * (cb.w - cb.y);
            bool sup = false;
            for (int p = lane; p < npick; p += 32) {
                if (s_plab[p] == lbl) {
                    float4 pb = s_pbox[p];
                    float xx1 = fmaxf(pb.x, cb.x);
                    float yy1 = fmaxf(pb.y, cb.y);
                    float xx2 = fminf(pb.z, cb.z);
                    float yy2 = fminf(pb.w, cb.w);
                    float inter = fmaxf(xx2 - xx1, 0.0f) * fmaxf(yy2 - yy1, 0.0f);
                    float uni = s_par[p] + aj - inter;
                    float iou = inter / fmaxf(uni, 1e-9f);
                    sup |= (iou > IOU_THR);
                }
            }
            if (!__any_sync(0xffffffffu, sup)) {
                if (lane == 0) {
                    s_pbox[npick] = cb;
                    s_par[npick] = aj;
                    s_plab[npick] = lbl;
                    s_pkj[npick] = j;
                }
                __syncwarp();
                npick++;
            }
        }
        if (lane == 0) {
            for (; npick < NPOST; ++npick) s_pkj[npick] = 0;
        }
    }
    __syncthreads();

    // ---- Phase 7: outputs [scores | labels | boxes] f32 ----
    if (tid < NPOST) {
        const int k = tid;
        int j = s_pkj[k];
        unsigned long long key = U.s.keys[j];
        float score = __uint_as_float((unsigned int)(key >> 32));
        int idx = (int)(~(unsigned int)key);
        int q = idx / NC, lbl = idx - q * NC;
        float4 b = bx4[q];
        float x1 = (b.x - 0.5f * b.z) * img_w;
        float y1 = (b.y - 0.5f * b.w) * img_h;
        float x2 = (b.x + 0.5f * b.z) * img_w;
        float y2 = (b.y + 0.5f * b.w) * img_h;

        out[(size_t)img * NPOST + k] = score;
        out[(size_t)BS * NPOST + (size_t)img * NPOST + k] = (float)lbl;
        float* ob = out + (size_t)2 * BS * NPOST + ((size_t)img * NPOST + k) * 4;
        ob[0] = x1; ob[1] = y1; ob[2] = x2; ob[3] = y2;
    }
}

extern "C" void kernel_launch(void* const* d_in, const int* in_sizes, int n_in,
                              void* d_out, int out_size) {
    const float* pred_logits  = (const float*)d_in[0]; // [128,900,91]
    const float* pred_boxes   = (const float*)d_in[1]; // [128,900,4]
    const float* target_sizes = (const float*)d_in[2]; // [128,2]
    float* out = (float*)d_out;                        // 76800 f32
    (void)in_sizes; (void)n_in; (void)out_size;
    nms_post_kernel<<<BS, NTHREADS>>>(pred_logits, pred_boxes, target_sizes, out);
}

// round 3
// speedup vs baseline: 1.5911x; 1.1837x over previous
#include <cuda_runtime.h>
#include <cstdint>

#define BS      128
#define NQ      900
#define NC      91
#define NTOT    (NQ * NC)     /* 81900 */
#define NVEC    (NTOT / 4)    /* 20475 */
#define TSEL    256           /* threads-above-threshold target */
#define SORT_N  512
#define NPOST   100
#define NBINS   8192          /* 13-bit ordered-float bins */
#define NTHREADS 1024
#define IOU_THR 0.7f

// ---- XLA logistic replica: 0.5 + 0.5 * fast_tanh(0.5 * x), non-fused ----
__device__ __forceinline__ float xla_logistic(float x) {
    float t_in = __fmul_rn(x, 0.5f);
    float ax = fabsf(t_in);
    float t;
    if (ax < 0.0004f) {
        t = t_in;
    } else {
        float xc = fminf(fmaxf(t_in, -9.0f), 9.0f);
        float x2 = __fmul_rn(xc, xc);
        float p = -2.76076847742355e-16f;
        p = __fadd_rn(__fmul_rn(p, x2), 2.00018790482477e-13f);
        p = __fadd_rn(__fmul_rn(p, x2), -8.60467152213735e-11f);
        p = __fadd_rn(__fmul_rn(p, x2), 5.12229709037114e-08f);
        p = __fadd_rn(__fmul_rn(p, x2), 1.48572235717979e-05f);
        p = __fadd_rn(__fmul_rn(p, x2), 6.37261928875436e-04f);
        p = __fadd_rn(__fmul_rn(p, x2), 4.89352455891786e-03f);
        p = __fmul_rn(p, xc);
        float q = 1.19825839466702e-06f;
        q = __fadd_rn(__fmul_rn(q, x2), 1.18534705686654e-04f);
        q = __fadd_rn(__fmul_rn(q, x2), 2.26843463243900e-03f);
        q = __fadd_rn(__fmul_rn(q, x2), 4.89352518554385e-03f);
        t = __fdiv_rn(p, q);
    }
    return __fadd_rn(0.5f, __fmul_rn(0.5f, t));
}

__device__ __forceinline__ unsigned int ordered_bits(float x) {
    unsigned int u = __float_as_uint(x);
    int s = ((int)u) >> 31;
    return u ^ ((unsigned int)s | 0x80000000u);
}

__device__ __forceinline__ unsigned int inv_ordered(unsigned int ob) {
    return (ob & 0x80000000u) ? (ob ^ 0x80000000u) : ~ob;
}

struct __align__(16) ShKeysBoxes {
    unsigned long long keys[SORT_N];   // 4 KB
    float4 cbox[SORT_N];               // 8 KB
    int    clab[SORT_N];               // 2 KB
};

__global__ __launch_bounds__(NTHREADS, 1)
void nms_post_kernel(const float* __restrict__ logits,
                     const float* __restrict__ boxes,
                     const float* __restrict__ tsz,
                     float* __restrict__ out) {
    __shared__ union {
        unsigned int hist[NBINS];      // 32 KB (phase 2 only)
        ShKeysBoxes  s;                // 14 KB (phases 3+)
    } U;
    __shared__ unsigned int s_coarse[NTHREADS];  // 4 KB
    __shared__ unsigned int s_wtot[32];
    __shared__ int s_pkj[NPOST];
    __shared__ int s_cnt, s_bin, s_g;

    const int img = blockIdx.x;
    const int tid = threadIdx.x;
    const int lane = tid & 31;
    const int wid = tid >> 5;

    const float*  lg  = logits + (size_t)img * NTOT;
    const float4* lg4 = reinterpret_cast<const float4*>(lg);
    const float*  bxp = boxes + (size_t)img * NQ * 4;
    const float4* bx4 = reinterpret_cast<const float4*>(bxp);
    const float img_h = tsz[img * 2 + 0];
    const float img_w = tsz[img * 2 + 1];

    // ---- Phase 1: single read pass, 4 batched LDG.128 per iter (MLP=4);
    //      per-thread top-4 keys in registers ----
    unsigned long long k0 = 0, k1 = 0, k2 = 0, k3 = 0;
    unsigned int k3h = 0;
    for (int base = 0; base < NVEC; base += 4 * NTHREADS) {
        const int i0 = base + tid;
        const int i1 = i0 + NTHREADS;
        const int i2 = i1 + NTHREADS;
        const int i3 = i2 + NTHREADS;
        // front-batched guarded loads (independent -> 4 in flight)
        float4 v0 = (i0 < NVEC) ? lg4[i0] : make_float4(0.f, 0.f, 0.f, 0.f);
        float4 v1 = (i1 < NVEC) ? lg4[i1] : make_float4(0.f, 0.f, 0.f, 0.f);
        float4 v2 = (i2 < NVEC) ? lg4[i2] : make_float4(0.f, 0.f, 0.f, 0.f);
        float4 v3 = (i3 < NVEC) ? lg4[i3] : make_float4(0.f, 0.f, 0.f, 0.f);
        const float4 vs[4] = {v0, v1, v2, v3};
        const int    is[4] = {i0, i1, i2, i3};
        #pragma unroll
        for (int u = 0; u < 4; ++u) {
            if (is[u] < NVEC) {
                const float vv[4] = {vs[u].x, vs[u].y, vs[u].z, vs[u].w};
                const int ebase = is[u] * 4;
                #pragma unroll
                for (int c = 0; c < 4; ++c) {
                    unsigned int ob = ordered_bits(vv[c]);
                    if (ob >= k3h) {
                        unsigned long long key =
                            ((unsigned long long)ob << 32) | (unsigned int)(~(ebase + c));
                        if (key > k3) {
                            if (key > k1) {
                                if (key > k0) { k3 = k2; k2 = k1; k1 = k0; k0 = key; }
                                else          { k3 = k2; k2 = k1; k1 = key; }
                            } else {
                                if (key > k2) { k3 = k2; k2 = key; }
                                else          { k3 = key; }
                            }
                            k3h = (unsigned int)(k3 >> 32);
                        }
                    }
                }
            }
        }
    }

    // ---- Phase 2: histogram of per-thread MAX (1024 atomics) -> threshold ----
    for (int i = tid; i < NBINS; i += NTHREADS) U.hist[i] = 0u;
    __syncthreads();
    atomicAdd(&U.hist[(unsigned int)(k0 >> 32) >> 19], 1u);
    __syncthreads();

    // coarse sums (8 bins per thread), then shfl-based inclusive suffix scan
    unsigned int csum;
    {
        int b8 = tid * 8;
        csum = 0;
        #pragma unroll
        for (int c = 0; c < 8; ++c) csum += U.hist[b8 + c];
    }
    {
        unsigned int val = csum;
        #pragma unroll
        for (int off = 1; off < 32; off <<= 1) {
            unsigned int v = __shfl_down_sync(0xffffffffu, val, off);
            if (lane + off < 32) val += v;
        }
        if (lane == 0) s_wtot[wid] = val;   // warp totals
        __syncthreads();
        if (tid < 32) {
            unsigned int w = s_wtot[tid];
            #pragma unroll
            for (int off = 1; off < 32; off <<= 1) {
                unsigned int v = __shfl_down_sync(0xffffffffu, w, off);
                if (tid + off < 32) w += v;
            }
            s_wtot[tid] = w;                // inclusive suffix of warp totals
        }
        __syncthreads();
        unsigned int above = val + ((wid < 31) ? s_wtot[wid + 1] : 0u);
        s_coarse[tid] = above;              // inclusive suffix over coarse bins
    }
    __syncthreads();
    {
        unsigned int mine = s_coarse[tid];
        unsigned int nxt = (tid < NTHREADS - 1) ? s_coarse[tid + 1] : 0u;
        if (mine >= TSEL && nxt < TSEL) s_g = tid;   // unique crossing
    }
    __syncthreads();
    if (tid == 0) {
        int g = s_g;
        unsigned int cum = (g < NTHREADS - 1) ? s_coarse[g + 1] : 0u;
        int b = g * 8;
        for (int bin = g * 8 + 7; bin >= g * 8; --bin) {
            cum += U.hist[bin];
            if (cum >= TSEL) { b = bin; break; }
        }
        s_bin = b;
        s_cnt = 0;
    }
    __syncthreads();
    const unsigned int bthr = (unsigned int)s_bin;
    __syncthreads();   // all hist reads complete before keys overwrite it

    // ---- Phase 3: collect register candidates above threshold bin ----
    for (int i = tid; i < SORT_N; i += NTHREADS) U.s.keys[i] = 0ull;
    __syncthreads();
    {
        unsigned long long cand[4] = {k0, k1, k2, k3};
        #pragma unroll
        for (int c = 0; c < 4; ++c) {
            unsigned int ob = (unsigned int)(cand[c] >> 32);
            if ((ob >> 19) >= bthr) {
                float x = __uint_as_float(inv_ordered(ob));
                float p = xla_logistic(x);
                int pos = atomicAdd(&s_cnt, 1);
                if (pos < SORT_N) {
                    U.s.keys[pos] = ((unsigned long long)__float_as_uint(p) << 32)
                                  | (unsigned int)(cand[c]);   // low 32 = ~idx
                }
            }
        }
    }
    __syncthreads();
    const int cnt = (s_cnt < SORT_N) ? s_cnt : SORT_N;

    // ---- Phase 4: bitonic sort 512 keys descending (prob desc, idx asc) ----
    for (int k = 2; k <= SORT_N; k <<= 1) {
        for (int j = k >> 1; j > 0; j >>= 1) {
            if (tid < SORT_N) {
                int l = tid ^ j;
                if (l > tid) {
                    unsigned long long a = U.s.keys[tid];
                    unsigned long long b = U.s.keys[l];
                    bool desc = ((tid & k) == 0);
                    if (desc ? (a < b) : (a > b)) {
                        U.s.keys[tid] = b;
                        U.s.keys[l] = a;
                    }
                }
            }
            __syncthreads();
        }
    }

    // ---- Phase 5: precompute scaled xyxy boxes for all candidates ----
    if (tid < SORT_N) {
        const int j = tid;
        if (j < cnt) {
            unsigned long long key = U.s.keys[j];
            int idx = (int)(~(unsigned int)key);
            int q = idx / NC, lbl = idx - q * NC;
            float4 b = bx4[q];                       // cx, cy, w, h
            float x1 = (b.x - 0.5f * b.z) * img_w;
            float y1 = (b.y - 0.5f * b.w) * img_h;
            float x2 = (b.x + 0.5f * b.z) * img_w;
            float y2 = (b.y + 0.5f * b.w) * img_h;
            U.s.cbox[j] = make_float4(x1, y1, x2, y2);
            U.s.clab[j] = lbl;
        } else {
            U.s.clab[j] = -1;
        }
    }
    __syncthreads();

    // ---- Phase 6: sequential greedy class-aware NMS (warp 0),
    //      pick list register-resident: lane L holds picks p%32==L ----
    if (tid < 32) {
        float4 rb[4];
        float  rar[4];
        int    rlab[4] = {-1, -1, -1, -1};
        int npick = 0;
        for (int j = 0; j < cnt && npick < NPOST; ++j) {
            float4 cb = U.s.cbox[j];     // broadcast LDS
            int lbl = U.s.clab[j];
            float aj = (cb.z - cb.x) * (cb.w - cb.y);
            bool sup = false;
            #pragma unroll
            for (int s = 0; s < 4; ++s) {
                int p = s * 32 + lane;
                if (p < npick && rlab[s] == lbl) {
                    float xx1 = fmaxf(rb[s].x, cb.x);
                    float yy1 = fmaxf(rb[s].y, cb.y);
                    float xx2 = fminf(rb[s].z, cb.z);
                    float yy2 = fminf(rb[s].w, cb.w);
                    float inter = fmaxf(xx2 - xx1, 0.0f) * fmaxf(yy2 - yy1, 0.0f);
                    float uni = rar[s] + aj - inter;
                    float iou = inter / fmaxf(uni, 1e-9f);
                    sup |= (iou > IOU_THR);
                }
            }
            if (!__any_sync(0xffffffffu, sup)) {
                #pragma unroll
                for (int s = 0; s < 4; ++s) {
                    if ((npick >> 5) == s && (npick & 31) == lane) {
                        rb[s] = cb; rar[s] = aj; rlab[s] = lbl;
                    }
                }
                if (lane == 0) s_pkj[npick] = j;
                npick++;
            }
        }
        if (lane == 0) {
            for (; npick < NPOST; ++npick) s_pkj[npick] = 0;
        }
    }
    __syncthreads();

    // ---- Phase 7: outputs [scores | labels | boxes] f32 ----
    if (tid < NPOST) {
        const int k = tid;
        int j = s_pkj[k];
        unsigned long long key = U.s.keys[j];
        float score = __uint_as_float((unsigned int)(key >> 32));
        int idx = (int)(~(unsigned int)key);
        int q = idx / NC, lbl = idx - q * NC;
        float4 b = bx4[q];
        float x1 = (b.x - 0.5f * b.z) * img_w;
        float y1 = (b.y - 0.5f * b.w) * img_h;
        float x2 = (b.x + 0.5f * b.z) * img_w;
        float y2 = (b.y + 0.5f * b.w) * img_h;

        out[(size_t)img * NPOST + k] = score;
        out[(size_t)BS * NPOST + (size_t)img * NPOST + k] = (float)lbl;
        float* ob = out + (size_t)2 * BS * NPOST + ((size_t)img * NPOST + k) * 4;
        ob[0] = x1; ob[1] = y1; ob[2] = x2; ob[3] = y2;
    }
}

extern "C" void kernel_launch(void* const* d_in, const int* in_sizes, int n_in,
                              void* d_out, int out_size) {
    const float* pred_logits  = (const float*)d_in[0]; // [128,900,91]
    const float* pred_boxes   = (const float*)d_in[1]; // [128,900,4]
    const float* target_sizes = (const float*)d_in[2]; // [128,2]
    float* out = (float*)d_out;                        // 76800 f32
    (void)in_sizes; (void)n_in; (void)out_size;
    nms_post_kernel<<<BS, NTHREADS>>>(pred_logits, pred_boxes, target_sizes, out);
}

// round 4
// speedup vs baseline: 1.6200x; 1.0182x over previous
#include <cuda_runtime.h>
#include <cstdint>

#define BS      128
#define NQ      900
#define NC      91
#define NTOT    (NQ * NC)     /* 81900 */
#define NVEC    (NTOT / 4)    /* 20475 */
#define TSEL    256
#define SORT_N  512
#define NPOST   100
#define NBINS   8192
#define NTHREADS 1024
#define IOU_THR 0.7f

#define BAR512() asm volatile("bar.sync 1, 512;" ::: "memory")

// ---- XLA logistic replica: 0.5 + 0.5 * fast_tanh(0.5 * x), non-fused ----
__device__ __forceinline__ float xla_logistic(float x) {
    float t_in = __fmul_rn(x, 0.5f);
    float ax = fabsf(t_in);
    float t;
    if (ax < 0.0004f) {
        t = t_in;
    } else {
        float xc = fminf(fmaxf(t_in, -9.0f), 9.0f);
        float x2 = __fmul_rn(xc, xc);
        float p = -2.76076847742355e-16f;
        p = __fadd_rn(__fmul_rn(p, x2), 2.00018790482477e-13f);
        p = __fadd_rn(__fmul_rn(p, x2), -8.60467152213735e-11f);
        p = __fadd_rn(__fmul_rn(p, x2), 5.12229709037114e-08f);
        p = __fadd_rn(__fmul_rn(p, x2), 1.48572235717979e-05f);
        p = __fadd_rn(__fmul_rn(p, x2), 6.37261928875436e-04f);
        p = __fadd_rn(__fmul_rn(p, x2), 4.89352455891786e-03f);
        p = __fmul_rn(p, xc);
        float q = 1.19825839466702e-06f;
        q = __fadd_rn(__fmul_rn(q, x2), 1.18534705686654e-04f);
        q = __fadd_rn(__fmul_rn(q, x2), 2.26843463243900e-03f);
        q = __fadd_rn(__fmul_rn(q, x2), 4.89352518554385e-03f);
        t = __fdiv_rn(p, q);
    }
    return __fadd_rn(0.5f, __fmul_rn(0.5f, t));
}

__device__ __forceinline__ unsigned int ordered_bits(float x) {
    unsigned int u = __float_as_uint(x);
    int s = ((int)u) >> 31;
    return u ^ ((unsigned int)s | 0x80000000u);
}

__device__ __forceinline__ unsigned int inv_ordered(unsigned int ob) {
    return (ob & 0x80000000u) ? (ob ^ 0x80000000u) : ~ob;
}

// exact top-4 insertion of one element
__device__ __forceinline__ void ins4(unsigned int ob, int idx,
                                     unsigned long long& k0, unsigned long long& k1,
                                     unsigned long long& k2, unsigned long long& k3,
                                     unsigned int& k3h) {
    if (ob >= k3h) {
        unsigned long long key = ((unsigned long long)ob << 32) | (unsigned int)(~idx);
        if (key > k3) {
            if (key > k1) {
                if (key > k0) { k3 = k2; k2 = k1; k1 = k0; k0 = key; }
                else          { k3 = k2; k2 = k1; k1 = key; }
            } else {
                if (key > k2) { k3 = k2; k2 = key; }
                else          { k3 = key; }
            }
            k3h = (unsigned int)(k3 >> 32);
        }
    }
}

// bitonic in-warp exchange steps j = jstart .. 1 (element index == tid)
__device__ __forceinline__ unsigned long long
bitonic_inwarp(unsigned long long key, int tid, int k, int jstart) {
    for (int j = jstart; j > 0; j >>= 1) {
        unsigned long long other = __shfl_xor_sync(0xffffffffu, key, j);
        bool take_max = (((tid & k) == 0) == ((tid & j) == 0));
        bool gt = key > other;
        key = (take_max == gt) ? key : other;
    }
    return key;
}

struct __align__(16) ShKeysBoxes {
    unsigned long long keys[SORT_N];   // 4 KB
    float4 cbox[SORT_N];               // 8 KB
    float  area[SORT_N];               // 2 KB
    int    clab[SORT_N];               // 2 KB
};

__global__ __launch_bounds__(NTHREADS, 1)
void nms_post_kernel(const float* __restrict__ logits,
                     const float* __restrict__ boxes,
                     const float* __restrict__ tsz,
                     float* __restrict__ out) {
    __shared__ union {
        unsigned int hist[NBINS];      // 32 KB (phase 2 only)
        ShKeysBoxes  s;                // 16 KB (phases 3+)
    } U;
    __shared__ unsigned int s_coarse[NTHREADS];
    __shared__ unsigned int s_wtot[32];
    __shared__ int s_pkj[NPOST];
    __shared__ int s_cnt, s_bin, s_g;

    const int img = blockIdx.x;
    const int tid = threadIdx.x;
    const int lane = tid & 31;
    const int wid = tid >> 5;

    const float*  lg  = logits + (size_t)img * NTOT;
    const float4* lg4 = reinterpret_cast<const float4*>(lg);
    const float4* bx4 = reinterpret_cast<const float4*>(boxes + (size_t)img * NQ * 4);
    const float img_h = tsz[img * 2 + 0];
    const float img_w = tsz[img * 2 + 1];

    const float NEG = __int_as_float(0xff800000);   // -inf
    const float4 NEG4 = make_float4(NEG, NEG, NEG, NEG);

    // ---- Phase 1: scan; per-thread exact top-4; fmax-tree fast path ----
    unsigned long long k0 = 0, k1 = 0, k2 = 0, k3 = 0;
    unsigned int k3h = 0;
    #pragma unroll 1
    for (int it = 0; it < 5; ++it) {
        const int i0 = it * (4 * NTHREADS) + tid;
        const int i1 = i0 + NTHREADS;
        const int i2 = i1 + NTHREADS;
        const int i3 = i2 + NTHREADS;
        float4 v0 = (i0 < NVEC) ? lg4[i0] : NEG4;
        float4 v1 = (i1 < NVEC) ? lg4[i1] : NEG4;
        float4 v2 = (i2 < NVEC) ? lg4[i2] : NEG4;
        float4 v3 = (i3 < NVEC) ? lg4[i3] : NEG4;
        // block max (branch-free tree)
        float m0 = fmaxf(fmaxf(v0.x, v0.y), fmaxf(v0.z, v0.w));
        float m1 = fmaxf(fmaxf(v1.x, v1.y), fmaxf(v1.z, v1.w));
        float m2 = fmaxf(fmaxf(v2.x, v2.y), fmaxf(v2.z, v2.w));
        float m3 = fmaxf(fmaxf(v3.x, v3.y), fmaxf(v3.z, v3.w));
        float bm = fmaxf(fmaxf(m0, m1), fmaxf(m2, m3));
        if (ordered_bits(bm) >= k3h) {     // >= catches value-ties exactly
            int b;
            b = i0 * 4;
            ins4(ordered_bits(v0.x), b + 0, k0, k1, k2, k3, k3h);
            ins4(ordered_bits(v0.y), b + 1, k0, k1, k2, k3, k3h);
            ins4(ordered_bits(v0.z), b + 2, k0, k1, k2, k3, k3h);
            ins4(ordered_bits(v0.w), b + 3, k0, k1, k2, k3, k3h);
            b = i1 * 4;
            ins4(ordered_bits(v1.x), b + 0, k0, k1, k2, k3, k3h);
            ins4(ordered_bits(v1.y), b + 1, k0, k1, k2, k3, k3h);
            ins4(ordered_bits(v1.z), b + 2, k0, k1, k2, k3, k3h);
            ins4(ordered_bits(v1.w), b + 3, k0, k1, k2, k3, k3h);
            b = i2 * 4;
            ins4(ordered_bits(v2.x), b + 0, k0, k1, k2, k3, k3h);
            ins4(ordered_bits(v2.y), b + 1, k0, k1, k2, k3, k3h);
            ins4(ordered_bits(v2.z), b + 2, k0, k1, k2, k3, k3h);
            ins4(ordered_bits(v2.w), b + 3, k0, k1, k2, k3, k3h);
            b = i3 * 4;
            ins4(ordered_bits(v3.x), b + 0, k0, k1, k2, k3, k3h);
            ins4(ordered_bits(v3.y), b + 1, k0, k1, k2, k3, k3h);
            ins4(ordered_bits(v3.z), b + 2, k0, k1, k2, k3, k3h);
            ins4(ordered_bits(v3.w), b + 3, k0, k1, k2, k3, k3h);
        }
    }

    // ---- Phase 2: histogram of per-thread MAX -> threshold bin ----
    for (int i = tid; i < NBINS; i += NTHREADS) U.hist[i] = 0u;
    __syncthreads();
    atomicAdd(&U.hist[(unsigned int)(k0 >> 32) >> 19], 1u);
    __syncthreads();
    unsigned int csum;
    {
        int b8 = tid * 8;
        csum = 0;
        #pragma unroll
        for (int c = 0; c < 8; ++c) csum += U.hist[b8 + c];
    }
    {
        unsigned int val = csum;
        #pragma unroll
        for (int off = 1; off < 32; off <<= 1) {
            unsigned int v = __shfl_down_sync(0xffffffffu, val, off);
            if (lane + off < 32) val += v;
        }
        if (lane == 0) s_wtot[wid] = val;
        __syncthreads();
        if (tid < 32) {
            unsigned int w = s_wtot[tid];
            #pragma unroll
            for (int off = 1; off < 32; off <<= 1) {
                unsigned int v = __shfl_down_sync(0xffffffffu, w, off);
                if (tid + off < 32) w += v;
            }
            s_wtot[tid] = w;
        }
        __syncthreads();
        s_coarse[tid] = val + ((wid < 31) ? s_wtot[wid + 1] : 0u);
    }
    __syncthreads();
    {
        unsigned int mine = s_coarse[tid];
        unsigned int nxt = (tid < NTHREADS - 1) ? s_coarse[tid + 1] : 0u;
        if (mine >= TSEL && nxt < TSEL) s_g = tid;
    }
    __syncthreads();
    if (tid == 0) {
        int g = s_g;
        unsigned int cum = (g < NTHREADS - 1) ? s_coarse[g + 1] : 0u;
        int b = g * 8;
        for (int bin = g * 8 + 7; bin >= g * 8; --bin) {
            cum += U.hist[bin];
            if (cum >= TSEL) { b = bin; break; }
        }
        s_bin = b;
        s_cnt = 0;
    }
    __syncthreads();
    const unsigned int bthr = (unsigned int)s_bin;
    __syncthreads();   // all hist reads done before keys alias

    // ---- Phase 3: collect candidates ----
    for (int i = tid; i < SORT_N; i += NTHREADS) U.s.keys[i] = 0ull;
    __syncthreads();
    {
        unsigned long long cand[4] = {k0, k1, k2, k3};
        #pragma unroll
        for (int c = 0; c < 4; ++c) {
            unsigned int ob = (unsigned int)(cand[c] >> 32);
            if ((ob >> 19) >= bthr) {
                float x = __uint_as_float(inv_ordered(ob));
                float p = xla_logistic(x);
                int pos = atomicAdd(&s_cnt, 1);
                if (pos < SORT_N) {
                    U.s.keys[pos] = ((unsigned long long)__float_as_uint(p) << 32)
                                  | (unsigned int)(cand[c]);
                }
            }
        }
    }
    __syncthreads();
    const int cnt = (s_cnt < SORT_N) ? s_cnt : SORT_N;

    // ---- Phase 4: hybrid bitonic sort (desc), 512 keys, 512 threads ----
    if (tid < SORT_N) {
        unsigned long long key = U.s.keys[tid];
        #pragma unroll
        for (int k = 2; k <= 32; k <<= 1)
            key = bitonic_inwarp(key, tid, k, k >> 1);
        U.s.keys[tid] = key;
        BAR512();
        #pragma unroll
        for (int k = 64; k <= SORT_N; k <<= 1) {
            for (int j = k >> 1; j >= 32; j >>= 1) {
                int l = tid ^ j;
                if (l > tid) {
                    unsigned long long a = U.s.keys[tid];
                    unsigned long long b = U.s.keys[l];
                    bool desc = ((tid & k) == 0);
                    if (desc ? (a < b) : (a > b)) {
                        U.s.keys[tid] = b;
                        U.s.keys[l] = a;
                    }
                }
                BAR512();
            }
            key = U.s.keys[tid];
            key = bitonic_inwarp(key, tid, k, 16);
            U.s.keys[tid] = key;
            BAR512();
        }
    }
    __syncthreads();

    // ---- Phase 5: precompute scaled xyxy boxes + areas ----
    if (tid < SORT_N) {
        const int j = tid;
        if (j < cnt) {
            unsigned long long key = U.s.keys[j];
            int idx = (int)(~(unsigned int)key);
            int q = idx / NC, lbl = idx - q * NC;
            float4 b = bx4[q];
            float x1 = (b.x - 0.5f * b.z) * img_w;
            float y1 = (b.y - 0.5f * b.w) * img_h;
            float x2 = (b.x + 0.5f * b.z) * img_w;
            float y2 = (b.y + 0.5f * b.w) * img_h;
            U.s.cbox[j] = make_float4(x1, y1, x2, y2);
            U.s.area[j] = (x2 - x1) * (y2 - y1);
            U.s.clab[j] = lbl;
        } else {
            U.s.cbox[j] = make_float4(0.f, 0.f, 0.f, 0.f);
            U.s.area[j] = 0.f;
            U.s.clab[j] = -1;
        }
    }
    __syncthreads();

    // ---- Phase 6: serial greedy NMS (warp 0), reg-resident picks, prefetch ----
    if (tid < 32) {
        float4 rb[4];
        float  rar[4];
        int    rlab[4] = {-1, -1, -1, -1};
        int npick = 0;
        float4 cb = U.s.cbox[0];
        float  aj = U.s.area[0];
        int    lbl = U.s.clab[0];
        for (int j = 0; j < cnt && npick < NPOST; ++j) {
            int jn = (j + 1 < SORT_N) ? j + 1 : j;
            float4 nb = U.s.cbox[jn];     // prefetch (hides LDS latency)
            float  na = U.s.area[jn];
            int    nl = U.s.clab[jn];
            bool sup = false;
            #pragma unroll
            for (int s = 0; s < 4; ++s) {
                int p = s * 32 + lane;
                if (p < npick && rlab[s] == lbl) {
                    float xx1 = fmaxf(rb[s].x, cb.x);
                    float yy1 = fmaxf(rb[s].y, cb.y);
                    float xx2 = fminf(rb[s].z, cb.z);
                    float yy2 = fminf(rb[s].w, cb.w);
                    float inter = fmaxf(xx2 - xx1, 0.0f) * fmaxf(yy2 - yy1, 0.0f);
                    float uni = rar[s] + aj - inter;
                    float iou = inter / fmaxf(uni, 1e-9f);
                    sup |= (iou > IOU_THR);
                }
            }
            if (!__any_sync(0xffffffffu, sup)) {
                #pragma unroll
                for (int s = 0; s < 4; ++s) {
                    if ((npick >> 5) == s && (npick & 31) == lane) {
                        rb[s] = cb; rar[s] = aj; rlab[s] = lbl;
                    }
                }
                if (lane == 0) s_pkj[npick] = j;
                npick++;
            }
            cb = nb; aj = na; lbl = nl;
        }
        if (lane == 0) {
            for (; npick < NPOST; ++npick) s_pkj[npick] = 0;
        }
    }
    __syncthreads();

    // ---- Phase 7: outputs [scores | labels | boxes] f32 ----
    if (tid < NPOST) {
        const int k = tid;
        int j = s_pkj[k];
        unsigned long long key = U.s.keys[j];
        float score = __uint_as_float((unsigned int)(key >> 32));
        int idx = (int)(~(unsigned int)key);
        int q = idx / NC, lbl = idx - q * NC;
        float4 b = bx4[q];
        float x1 = (b.x - 0.5f * b.z) * img_w;
        float y1 = (b.y - 0.5f * b.w) * img_h;
        float x2 = (b.x + 0.5f * b.z) * img_w;
        float y2 = (b.y + 0.5f * b.w) * img_h;

        out[(size_t)img * NPOST + k] = score;
        out[(size_t)BS * NPOST + (size_t)img * NPOST + k] = (float)lbl;
        float* ob = out + (size_t)2 * BS * NPOST + ((size_t)img * NPOST + k) * 4;
        ob[0] = x1; ob[1] = y1; ob[2] = x2; ob[3] = y2;
    }
}

extern "C" void kernel_launch(void* const* d_in, const int* in_sizes, int n_in,
                              void* d_out, int out_size) {
    const float* pred_logits  = (const float*)d_in[0];
    const float* pred_boxes   = (const float*)d_in[1];
    const float* target_sizes = (const float*)d_in[2];
    float* out = (float*)d_out;
    (void)in_sizes; (void)n_in; (void)out_size;
    nms_post_kernel<<<BS, NTHREADS>>>(pred_logits, pred_boxes, target_sizes, out);
}

// round 5
// speedup vs baseline: 1.8768x; 1.1585x over previous
#include <cuda_runtime.h>
#include <cstdint>

#define BS      128
#define NQ      900
#define NC      91
#define NTOT    (NQ * NC)     /* 81900 */
#define NVEC    (NTOT / 4)    /* 20475 */
#define TSEL    256
#define SORT_N  512
#define NPOST   100
#define NBINS   8192
#define NTHREADS 1024
#define IOU_THR 0.7f

#define BAR512() asm volatile("bar.sync 1, 512;" ::: "memory")

// ---- XLA logistic replica: 0.5 + 0.5 * fast_tanh(0.5 * x), non-fused ----
__device__ __forceinline__ float xla_logistic(float x) {
    float t_in = __fmul_rn(x, 0.5f);
    float ax = fabsf(t_in);
    float t;
    if (ax < 0.0004f) {
        t = t_in;
    } else {
        float xc = fminf(fmaxf(t_in, -9.0f), 9.0f);
        float x2 = __fmul_rn(xc, xc);
        float p = -2.76076847742355e-16f;
        p = __fadd_rn(__fmul_rn(p, x2), 2.00018790482477e-13f);
        p = __fadd_rn(__fmul_rn(p, x2), -8.60467152213735e-11f);
        p = __fadd_rn(__fmul_rn(p, x2), 5.12229709037114e-08f);
        p = __fadd_rn(__fmul_rn(p, x2), 1.48572235717979e-05f);
        p = __fadd_rn(__fmul_rn(p, x2), 6.37261928875436e-04f);
        p = __fadd_rn(__fmul_rn(p, x2), 4.89352455891786e-03f);
        p = __fmul_rn(p, xc);
        float q = 1.19825839466702e-06f;
        q = __fadd_rn(__fmul_rn(q, x2), 1.18534705686654e-04f);
        q = __fadd_rn(__fmul_rn(q, x2), 2.26843463243900e-03f);
        q = __fadd_rn(__fmul_rn(q, x2), 4.89352518554385e-03f);
        t = __fdiv_rn(p, q);
    }
    return __fadd_rn(0.5f, __fmul_rn(0.5f, t));
}

__device__ __forceinline__ unsigned int ordered_bits(float x) {
    unsigned int u = __float_as_uint(x);
    int s = ((int)u) >> 31;
    return u ^ ((unsigned int)s | 0x80000000u);
}

__device__ __forceinline__ unsigned int inv_ordered(unsigned int ob) {
    return (ob & 0x80000000u) ? (ob ^ 0x80000000u) : ~ob;
}

// bitonic in-warp exchange steps j = jstart .. 1 (element index == tid)
__device__ __forceinline__ unsigned long long
bitonic_inwarp(unsigned long long key, int tid, int k, int jstart) {
    for (int j = jstart; j > 0; j >>= 1) {
        unsigned long long other = __shfl_xor_sync(0xffffffffu, key, j);
        bool take_max = (((tid & k) == 0) == ((tid & j) == 0));
        bool gt = key > other;
        key = (take_max == gt) ? key : other;
    }
    return key;
}

struct __align__(16) ShKeysBoxes {
    unsigned long long keys[SORT_N];   // 4 KB
    float4 cbox[SORT_N];               // 8 KB
    float  area[SORT_N];               // 2 KB
    int    clab[SORT_N];               // 2 KB
};

__global__ __launch_bounds__(NTHREADS, 1)
void nms_post_kernel(const float* __restrict__ logits,
                     const float* __restrict__ boxes,
                     const float* __restrict__ tsz,
                     float* __restrict__ out) {
    __shared__ union {
        unsigned int hist[NBINS];      // 32 KB (threshold phase only)
        ShKeysBoxes  s;                // 16 KB (later phases)
    } U;
    __shared__ unsigned int s_coarse[NTHREADS];
    __shared__ unsigned int s_wtot[32];
    __shared__ int s_pkj[NPOST];
    __shared__ int s_cnt, s_bin, s_g;

    const int img = blockIdx.x;
    const int tid = threadIdx.x;
    const int lane = tid & 31;
    const int wid = tid >> 5;

    const float4* lg4 = reinterpret_cast<const float4*>(logits + (size_t)img * NTOT);
    const float4* bx4 = reinterpret_cast<const float4*>(boxes + (size_t)img * NQ * 4);
    const float img_h = tsz[img * 2 + 0];
    const float img_w = tsz[img * 2 + 1];

    const float NEG = __int_as_float(0xff800000);   // -inf
    const float4 NEG4 = make_float4(NEG, NEG, NEG, NEG);

    // ---- Pass A: branch-free per-thread max over ~80 elements (MLP=4) ----
    float m = NEG;
    #pragma unroll 1
    for (int it = 0; it < 5; ++it) {
        const int i0 = it * (4 * NTHREADS) + tid;
        const int i1 = i0 + NTHREADS;
        const int i2 = i1 + NTHREADS;
        const int i3 = i2 + NTHREADS;
        float4 v0 = (i0 < NVEC) ? lg4[i0] : NEG4;
        float4 v1 = (i1 < NVEC) ? lg4[i1] : NEG4;
        float4 v2 = (i2 < NVEC) ? lg4[i2] : NEG4;
        float4 v3 = (i3 < NVEC) ? lg4[i3] : NEG4;
        float m0 = fmaxf(fmaxf(v0.x, v0.y), fmaxf(v0.z, v0.w));
        float m1 = fmaxf(fmaxf(v1.x, v1.y), fmaxf(v1.z, v1.w));
        float m2 = fmaxf(fmaxf(v2.x, v2.y), fmaxf(v2.z, v2.w));
        float m3 = fmaxf(fmaxf(v3.x, v3.y), fmaxf(v3.z, v3.w));
        m = fmaxf(m, fmaxf(fmaxf(m0, m1), fmaxf(m2, m3)));
    }

    // ---- Threshold: histogram of 1024 per-thread maxima -> bin ----
    for (int i = tid; i < NBINS; i += NTHREADS) U.hist[i] = 0u;
    __syncthreads();
    atomicAdd(&U.hist[ordered_bits(m) >> 19], 1u);
    __syncthreads();
    unsigned int csum;
    {
        int b8 = tid * 8;
        csum = 0;
        #pragma unroll
        for (int c = 0; c < 8; ++c) csum += U.hist[b8 + c];
    }
    {
        unsigned int val = csum;
        #pragma unroll
        for (int off = 1; off < 32; off <<= 1) {
            unsigned int v = __shfl_down_sync(0xffffffffu, val, off);
            if (lane + off < 32) val += v;
        }
        if (lane == 0) s_wtot[wid] = val;
        __syncthreads();
        if (tid < 32) {
            unsigned int w = s_wtot[tid];
            #pragma unroll
            for (int off = 1; off < 32; off <<= 1) {
                unsigned int v = __shfl_down_sync(0xffffffffu, w, off);
                if (tid + off < 32) w += v;
            }
            s_wtot[tid] = w;
        }
        __syncthreads();
        s_coarse[tid] = val + ((wid < 31) ? s_wtot[wid + 1] : 0u);
    }
    __syncthreads();
    {
        unsigned int mine = s_coarse[tid];
        unsigned int nxt = (tid < NTHREADS - 1) ? s_coarse[tid + 1] : 0u;
        if (mine >= TSEL && nxt < TSEL) s_g = tid;
    }
    __syncthreads();
    if (tid == 0) {
        int g = s_g;
        unsigned int cum = (g < NTHREADS - 1) ? s_coarse[g + 1] : 0u;
        int b = g * 8;
        for (int bin = g * 8 + 7; bin >= g * 8; --bin) {
            cum += U.hist[bin];
            if (cum >= TSEL) { b = bin; break; }
        }
        s_bin = b;
        s_cnt = 0;
    }
    __syncthreads();
    // bin compare (ob>>19) >= bthr  <=>  float compare v >= thr_float (exact)
    const float thr_float = __uint_as_float(inv_ordered((unsigned int)s_bin << 19));
    __syncthreads();   // all hist reads done before keys alias

    // ---- Pass B: L2-resident sweep; collect ALL elements >= threshold ----
    for (int i = tid; i < SORT_N; i += NTHREADS) U.s.keys[i] = 0ull;
    __syncthreads();
    #pragma unroll 1
    for (int it = 0; it < 5; ++it) {
        const int i0 = it * (4 * NTHREADS) + tid;
        const int i1 = i0 + NTHREADS;
        const int i2 = i1 + NTHREADS;
        const int i3 = i2 + NTHREADS;
        float4 v0 = (i0 < NVEC) ? lg4[i0] : NEG4;
        float4 v1 = (i1 < NVEC) ? lg4[i1] : NEG4;
        float4 v2 = (i2 < NVEC) ? lg4[i2] : NEG4;
        float4 v3 = (i3 < NVEC) ? lg4[i3] : NEG4;
        const float4 vs[4] = {v0, v1, v2, v3};
        const int    is[4] = {i0, i1, i2, i3};
        #pragma unroll
        for (int u = 0; u < 4; ++u) {
            const float vv[4] = {vs[u].x, vs[u].y, vs[u].z, vs[u].w};
            const int ebase = is[u] * 4;
            #pragma unroll
            for (int c = 0; c < 4; ++c) {
                if (vv[c] >= thr_float) {   // rare (~294/image across 81900)
                    float p = xla_logistic(vv[c]);
                    int pos = atomicAdd(&s_cnt, 1);
                    if (pos < SORT_N) {
                        U.s.keys[pos] =
                            ((unsigned long long)__float_as_uint(p) << 32)
                          | (unsigned int)(~(ebase + c));
                    }
                }
            }
        }
    }
    __syncthreads();
    const int cnt = (s_cnt < SORT_N) ? s_cnt : SORT_N;

    // ---- Sort: hybrid bitonic (desc), 512 keys, 512 threads ----
    if (tid < SORT_N) {
        unsigned long long key = U.s.keys[tid];
        #pragma unroll
        for (int k = 2; k <= 32; k <<= 1)
            key = bitonic_inwarp(key, tid, k, k >> 1);
        U.s.keys[tid] = key;
        BAR512();
        #pragma unroll
        for (int k = 64; k <= SORT_N; k <<= 1) {
            for (int j = k >> 1; j >= 32; j >>= 1) {
                int l = tid ^ j;
                if (l > tid) {
                    unsigned long long a = U.s.keys[tid];
                    unsigned long long b = U.s.keys[l];
                    bool desc = ((tid & k) == 0);
                    if (desc ? (a < b) : (a > b)) {
                        U.s.keys[tid] = b;
                        U.s.keys[l] = a;
                    }
                }
                BAR512();
            }
            key = U.s.keys[tid];
            key = bitonic_inwarp(key, tid, k, 16);
            U.s.keys[tid] = key;
            BAR512();
        }
    }
    __syncthreads();

    // ---- Precompute scaled xyxy boxes + areas ----
    if (tid < SORT_N) {
        const int j = tid;
        if (j < cnt) {
            unsigned long long key = U.s.keys[j];
            int idx = (int)(~(unsigned int)key);
            int q = idx / NC, lbl = idx - q * NC;
            float4 b = bx4[q];
            float x1 = (b.x - 0.5f * b.z) * img_w;
            float y1 = (b.y - 0.5f * b.w) * img_h;
            float x2 = (b.x + 0.5f * b.z) * img_w;
            float y2 = (b.y + 0.5f * b.w) * img_h;
            U.s.cbox[j] = make_float4(x1, y1, x2, y2);
            U.s.area[j] = (x2 - x1) * (y2 - y1);
            U.s.clab[j] = lbl;
        } else {
            U.s.cbox[j] = make_float4(0.f, 0.f, 0.f, 0.f);
            U.s.area[j] = 0.f;
            U.s.clab[j] = -1;
        }
    }
    __syncthreads();

    // ---- Serial greedy NMS (warp 0), reg-resident picks, prefetch ----
    if (tid < 32) {
        float4 rb[4];
        float  rar[4];
        int    rlab[4] = {-1, -1, -1, -1};
        int npick = 0;
        float4 cb = U.s.cbox[0];
        float  aj = U.s.area[0];
        int    lbl = U.s.clab[0];
        for (int j = 0; j < cnt && npick < NPOST; ++j) {
            int jn = (j + 1 < SORT_N) ? j + 1 : j;
            float4 nb = U.s.cbox[jn];
            float  na = U.s.area[jn];
            int    nl = U.s.clab[jn];
            bool sup = false;
            #pragma unroll
            for (int s = 0; s < 4; ++s) {
                int p = s * 32 + lane;
                if (p < npick && rlab[s] == lbl) {
                    float xx1 = fmaxf(rb[s].x, cb.x);
                    float yy1 = fmaxf(rb[s].y, cb.y);
                    float xx2 = fminf(rb[s].z, cb.z);
                    float yy2 = fminf(rb[s].w, cb.w);
                    float inter = fmaxf(xx2 - xx1, 0.0f) * fmaxf(yy2 - yy1, 0.0f);
                    float uni = rar[s] + aj - inter;
                    float iou = inter / fmaxf(uni, 1e-9f);
                    sup |= (iou > IOU_THR);
                }
            }
            if (!__any_sync(0xffffffffu, sup)) {
                #pragma unroll
                for (int s = 0; s < 4; ++s) {
                    if ((npick >> 5) == s && (npick & 31) == lane) {
                        rb[s] = cb; rar[s] = aj; rlab[s] = lbl;
                    }
                }
                if (lane == 0) s_pkj[npick] = j;
                npick++;
            }
            cb = nb; aj = na; lbl = nl;
        }
        if (lane == 0) {
            for (; npick < NPOST; ++npick) s_pkj[npick] = 0;
        }
    }
    __syncthreads();

    // ---- Outputs [scores | labels | boxes] f32 ----
    if (tid < NPOST) {
        const int k = tid;
        int j = s_pkj[k];
        unsigned long long key = U.s.keys[j];
        float score = __uint_as_float((unsigned int)(key >> 32));
        int idx = (int)(~(unsigned int)key);
        int q = idx / NC, lbl = idx - q * NC;
        float4 b = bx4[q];
        float x1 = (b.x - 0.5f * b.z) * img_w;
        float y1 = (b.y - 0.5f * b.w) * img_h;
        float x2 = (b.x + 0.5f * b.z) * img_w;
        float y2 = (b.y + 0.5f * b.w) * img_h;

        out[(size_t)img * NPOST + k] = score;
        out[(size_t)BS * NPOST + (size_t)img * NPOST + k] = (float)lbl;
        float* ob = out + (size_t)2 * BS * NPOST + ((size_t)img * NPOST + k) * 4;
        ob[0] = x1; ob[1] = y1; ob[2] = x2; ob[3] = y2;
    }
}

extern "C" void kernel_launch(void* const* d_in, const int* in_sizes, int n_in,
                              void* d_out, int out_size) {
    const float* pred_logits  = (const float*)d_in[0];
    const float* pred_boxes   = (const float*)d_in[1];
    const float* target_sizes = (const float*)d_in[2];
    float* out = (float*)d_out;
    (void)in_sizes; (void)n_in; (void)out_size;
    nms_post_kernel<<<BS, NTHREADS>>>(pred_logits, pred_boxes, target_sizes, out);
}

// round 6
// speedup vs baseline: 3.1087x; 1.6564x over previous
#include <cuda_runtime.h>
#include <cstdint>

#define BS      128
#define NQ      900
#define NC      91
#define NTOT    (NQ * NC)     /* 81900 */
#define NVEC    (NTOT / 4)    /* 20475 */
#define TSEL    256
#define SORT_N  512
#define NPOST   100
#define NBINS   8192
#define NTHREADS 1024
#define IOU_THR 0.7f
#define MROW    128           /* matrix-NMS depth */

#define BAR512() asm volatile("bar.sync 1, 512;" ::: "memory")

// ---- XLA logistic replica: 0.5 + 0.5 * fast_tanh(0.5 * x), non-fused ----
__device__ __forceinline__ float xla_logistic(float x) {
    float t_in = __fmul_rn(x, 0.5f);
    float ax = fabsf(t_in);
    float t;
    if (ax < 0.0004f) {
        t = t_in;
    } else {
        float xc = fminf(fmaxf(t_in, -9.0f), 9.0f);
        float x2 = __fmul_rn(xc, xc);
        float p = -2.76076847742355e-16f;
        p = __fadd_rn(__fmul_rn(p, x2), 2.00018790482477e-13f);
        p = __fadd_rn(__fmul_rn(p, x2), -8.60467152213735e-11f);
        p = __fadd_rn(__fmul_rn(p, x2), 5.12229709037114e-08f);
        p = __fadd_rn(__fmul_rn(p, x2), 1.48572235717979e-05f);
        p = __fadd_rn(__fmul_rn(p, x2), 6.37261928875436e-04f);
        p = __fadd_rn(__fmul_rn(p, x2), 4.89352455891786e-03f);
        p = __fmul_rn(p, xc);
        float q = 1.19825839466702e-06f;
        q = __fadd_rn(__fmul_rn(q, x2), 1.18534705686654e-04f);
        q = __fadd_rn(__fmul_rn(q, x2), 2.26843463243900e-03f);
        q = __fadd_rn(__fmul_rn(q, x2), 4.89352518554385e-03f);
        t = __fdiv_rn(p, q);
    }
    return __fadd_rn(0.5f, __fmul_rn(0.5f, t));
}

__device__ __forceinline__ unsigned int ordered_bits(float x) {
    unsigned int u = __float_as_uint(x);
    int s = ((int)u) >> 31;
    return u ^ ((unsigned int)s | 0x80000000u);
}

__device__ __forceinline__ unsigned int inv_ordered(unsigned int ob) {
    return (ob & 0x80000000u) ? (ob ^ 0x80000000u) : ~ob;
}

__device__ __forceinline__ unsigned long long
bitonic_inwarp(unsigned long long key, int tid, int k, int jstart) {
    for (int j = jstart; j > 0; j >>= 1) {
        unsigned long long other = __shfl_xor_sync(0xffffffffu, key, j);
        bool take_max = (((tid & k) == 0) == ((tid & j) == 0));
        bool gt = key > other;
        key = (take_max == gt) ? key : other;
    }
    return key;
}

struct __align__(16) ShKeysBoxes {
    unsigned long long keys[SORT_N];   // 4 KB
    float4 cbox[SORT_N];               // 8 KB
    float  area[SORT_N];               // 2 KB
    int    clab[SORT_N];               // 2 KB
};

__global__ __launch_bounds__(NTHREADS, 1)
void nms_post_kernel(const float* __restrict__ logits,
                     const float* __restrict__ boxes,
                     const float* __restrict__ tsz,
                     float* __restrict__ out) {
    extern __shared__ float s_bmax[];          // NVEC floats (81.9 KB dynamic)
    __shared__ union {
        unsigned int hist[NBINS];      // 32 KB (threshold phase only)
        ShKeysBoxes  s;                // 16 KB (later phases)
    } U;
    __shared__ unsigned int s_coarse[NTHREADS];
    __shared__ unsigned int s_wtot[32];
    __shared__ unsigned int s_mat[MROW * 4];   // suppression bits, 2 KB
    __shared__ float4 s_pbox[NPOST];
    __shared__ float  s_par[NPOST];
    __shared__ int    s_plab[NPOST];
    __shared__ int    s_pkj[NPOST];
    __shared__ int s_cnt, s_bin, s_g, s_np;

    const int img = blockIdx.x;
    const int tid = threadIdx.x;
    const int lane = tid & 31;
    const int wid = tid >> 5;

    const float4* lg4 = reinterpret_cast<const float4*>(logits + (size_t)img * NTOT);
    const float4* bx4 = reinterpret_cast<const float4*>(boxes + (size_t)img * NQ * 4);
    const float img_h = tsz[img * 2 + 0];
    const float img_w = tsz[img * 2 + 1];

    const float NEG = __int_as_float(0xff800000);   // -inf
    const float4 NEG4 = make_float4(NEG, NEG, NEG, NEG);

    // ---- Pass A: per-thread max (branch-free) + cache per-float4 maxima ----
    float m = NEG;
    #pragma unroll 1
    for (int it = 0; it < 5; ++it) {
        const int i0 = it * (4 * NTHREADS) + tid;
        const int i1 = i0 + NTHREADS;
        const int i2 = i1 + NTHREADS;
        const int i3 = i2 + NTHREADS;
        float4 v0 = (i0 < NVEC) ? lg4[i0] : NEG4;
        float4 v1 = (i1 < NVEC) ? lg4[i1] : NEG4;
        float4 v2 = (i2 < NVEC) ? lg4[i2] : NEG4;
        float4 v3 = (i3 < NVEC) ? lg4[i3] : NEG4;
        float m0 = fmaxf(fmaxf(v0.x, v0.y), fmaxf(v0.z, v0.w));
        float m1 = fmaxf(fmaxf(v1.x, v1.y), fmaxf(v1.z, v1.w));
        float m2 = fmaxf(fmaxf(v2.x, v2.y), fmaxf(v2.z, v2.w));
        float m3 = fmaxf(fmaxf(v3.x, v3.y), fmaxf(v3.z, v3.w));
        if (i0 < NVEC) s_bmax[i0] = m0;
        if (i1 < NVEC) s_bmax[i1] = m1;
        if (i2 < NVEC) s_bmax[i2] = m2;
        if (i3 < NVEC) s_bmax[i3] = m3;
        m = fmaxf(m, fmaxf(fmaxf(m0, m1), fmaxf(m2, m3)));
    }

    // ---- Threshold: histogram of 1024 per-thread maxima -> bin ----
    for (int i = tid; i < NBINS; i += NTHREADS) U.hist[i] = 0u;
    __syncthreads();
    atomicAdd(&U.hist[ordered_bits(m) >> 19], 1u);
    __syncthreads();
    unsigned int csum;
    {
        int b8 = tid * 8;
        csum = 0;
        #pragma unroll
        for (int c = 0; c < 8; ++c) csum += U.hist[b8 + c];
    }
    {
        unsigned int val = csum;
        #pragma unroll
        for (int off = 1; off < 32; off <<= 1) {
            unsigned int v = __shfl_down_sync(0xffffffffu, val, off);
            if (lane + off < 32) val += v;
        }
        if (lane == 0) s_wtot[wid] = val;
        __syncthreads();
        if (tid < 32) {
            unsigned int w = s_wtot[tid];
            #pragma unroll
            for (int off = 1; off < 32; off <<= 1) {
                unsigned int v = __shfl_down_sync(0xffffffffu, w, off);
                if (tid + off < 32) w += v;
            }
            s_wtot[tid] = w;
        }
        __syncthreads();
        s_coarse[tid] = val + ((wid < 31) ? s_wtot[wid + 1] : 0u);
    }
    __syncthreads();
    {
        unsigned int mine = s_coarse[tid];
        unsigned int nxt = (tid < NTHREADS - 1) ? s_coarse[tid + 1] : 0u;
        if (mine >= TSEL && nxt < TSEL) s_g = tid;
    }
    __syncthreads();
    if (tid == 0) {
        int g = s_g;
        unsigned int cum = (g < NTHREADS - 1) ? s_coarse[g + 1] : 0u;
        int b = g * 8;
        for (int bin = g * 8 + 7; bin >= g * 8; --bin) {
            cum += U.hist[bin];
            if (cum >= TSEL) { b = bin; break; }
        }
        s_bin = b;
        s_cnt = 0;
    }
    __syncthreads();
    const float thr_float = __uint_as_float(inv_ordered((unsigned int)s_bin << 19));
    __syncthreads();   // hist reads done before keys alias

    // ---- Pass B: SMEM block-max scan; reload only hot blocks from L2 ----
    for (int i = tid; i < SORT_N; i += NTHREADS) U.s.keys[i] = 0ull;
    __syncthreads();
    #pragma unroll 1
    for (int it = 0; it < 5; ++it) {
        const int i0 = it * (4 * NTHREADS) + tid;
        float bm[4];
        #pragma unroll
        for (int u = 0; u < 4; ++u) {
            int i = i0 + u * NTHREADS;
            bm[u] = (i < NVEC) ? s_bmax[i] : NEG;
        }
        #pragma unroll
        for (int u = 0; u < 4; ++u) {
            if (bm[u] >= thr_float) {          // ~1.4% of blocks
                int i = i0 + u * NTHREADS;
                float4 v = lg4[i];             // L2 hit
                const float vv[4] = {v.x, v.y, v.z, v.w};
                #pragma unroll
                for (int c = 0; c < 4; ++c) {
                    if (vv[c] >= thr_float) {
                        float p = xla_logistic(vv[c]);
                        int pos = atomicAdd(&s_cnt, 1);
                        if (pos < SORT_N) {
                            U.s.keys[pos] =
                                ((unsigned long long)__float_as_uint(p) << 32)
                              | (unsigned int)(~(i * 4 + c));
                        }
                    }
                }
            }
        }
    }
    __syncthreads();
    const int cnt = (s_cnt < SORT_N) ? s_cnt : SORT_N;

    // ---- Sort: hybrid bitonic (desc), 512 keys, 512 threads ----
    if (tid < SORT_N) {
        unsigned long long key = U.s.keys[tid];
        #pragma unroll
        for (int k = 2; k <= 32; k <<= 1)
            key = bitonic_inwarp(key, tid, k, k >> 1);
        U.s.keys[tid] = key;
        BAR512();
        #pragma unroll
        for (int k = 64; k <= SORT_N; k <<= 1) {
            for (int j = k >> 1; j >= 32; j >>= 1) {
                int l = tid ^ j;
                if (l > tid) {
                    unsigned long long a = U.s.keys[tid];
                    unsigned long long b = U.s.keys[l];
                    bool desc = ((tid & k) == 0);
                    if (desc ? (a < b) : (a > b)) {
                        U.s.keys[tid] = b;
                        U.s.keys[l] = a;
                    }
                }
                BAR512();
            }
            key = U.s.keys[tid];
            key = bitonic_inwarp(key, tid, k, 16);
            U.s.keys[tid] = key;
            BAR512();
        }
    }
    __syncthreads();

    // ---- Precompute scaled xyxy boxes + areas; zero suppression matrix ----
    if (tid < SORT_N) {
        const int j = tid;
        if (j < cnt) {
            unsigned long long key = U.s.keys[j];
            int idx = (int)(~(unsigned int)key);
            int q = idx / NC, lbl = idx - q * NC;
            float4 b = bx4[q];
            float x1 = (b.x - 0.5f * b.z) * img_w;
            float y1 = (b.y - 0.5f * b.w) * img_h;
            float x2 = (b.x + 0.5f * b.z) * img_w;
            float y2 = (b.y + 0.5f * b.w) * img_h;
            U.s.cbox[j] = make_float4(x1, y1, x2, y2);
            U.s.area[j] = (x2 - x1) * (y2 - y1);
            U.s.clab[j] = lbl;
        } else {
            U.s.cbox[j] = make_float4(0.f, 0.f, 0.f, 0.f);
            U.s.area[j] = 0.f;
            U.s.clab[j] = -1;
        }
    } else if (tid < SORT_N + MROW * 4) {
        s_mat[tid - SORT_N] = 0u;
    }
    __syncthreads();

    // ---- Matrix build: sup[i][j] for i,j < MROW (label-gated, div-free) ----
    {
        const int i = tid >> 3;          // 0..127
        const int seg = tid & 7;         // 0..7
        float4 bi = U.s.cbox[i];
        float  ai = U.s.area[i];
        int    li = U.s.clab[i];
        #pragma unroll
        for (int jj = 0; jj < 16; ++jj) {
            int j = jj * 8 + seg;        // conflict-free clab reads
            if (j != i && U.s.clab[j] == li && li >= 0) {
                float4 bj = U.s.cbox[j];
                float xx1 = fmaxf(bi.x, bj.x);
                float yy1 = fmaxf(bi.y, bj.y);
                float xx2 = fminf(bi.z, bj.z);
                float yy2 = fminf(bi.w, bj.w);
                float inter = fmaxf(xx2 - xx1, 0.0f) * fmaxf(yy2 - yy1, 0.0f);
                float uni = fmaxf(ai + U.s.area[j] - inter, 1e-9f);
                if (inter > IOU_THR * uni) {
                    atomicOr(&s_mat[i * 4 + (j >> 5)], 1u << (j & 31));
                }
            }
        }
    }
    __syncthreads();

    // ---- Serial walk over matrix (single thread, register mask) ----
    if (tid == 0) {
        unsigned int mk0 = 0, mk1 = 0, mk2 = 0, mk3 = 0;
        int npick = 0;
        const int jmax = (cnt < MROW) ? cnt : MROW;
        #define WALK_BLOCK(B, MK)                                           \
        for (int jo = 0; jo < 32; ++jo) {                                   \
            int j = (B) * 32 + jo;                                          \
            if (j >= jmax || npick >= NPOST) break;                         \
            if (!((MK >> jo) & 1u)) {                                       \
                s_pkj[npick] = j;                                           \
                s_pbox[npick] = U.s.cbox[j];                                \
                s_par[npick] = U.s.area[j];                                 \
                s_plab[npick] = U.s.clab[j];                                \
                npick++;                                                    \
                mk0 |= s_mat[j * 4 + 0];                                    \
                mk1 |= s_mat[j * 4 + 1];                                    \
                mk2 |= s_mat[j * 4 + 2];                                    \
                mk3 |= s_mat[j * 4 + 3];                                    \
            }                                                               \
        }
        WALK_BLOCK(0, mk0)
        WALK_BLOCK(1, mk1)
        WALK_BLOCK(2, mk2)
        WALK_BLOCK(3, mk3)
        #undef WALK_BLOCK
        s_np = npick;
    }
    __syncthreads();

    // ---- Fallback: serial warp NMS beyond MROW (rarely does work) ----
    if (tid < 32) {
        int npick = s_np;
        for (int j = MROW; j < cnt && npick < NPOST; ++j) {
            float4 cb = U.s.cbox[j];
            float  aj = U.s.area[j];
            int    lbl = U.s.clab[j];
            bool sup = false;
            for (int p = lane; p < npick; p += 32) {
                if (s_plab[p] == lbl) {
                    float4 pb = s_pbox[p];
                    float xx1 = fmaxf(pb.x, cb.x);
                    float yy1 = fmaxf(pb.y, cb.y);
                    float xx2 = fminf(pb.z, cb.z);
                    float yy2 = fminf(pb.w, cb.w);
                    float inter = fmaxf(xx2 - xx1, 0.0f) * fmaxf(yy2 - yy1, 0.0f);
                    float uni = fmaxf(s_par[p] + aj - inter, 1e-9f);
                    sup |= (inter > IOU_THR * uni);
                }
            }
            if (!__any_sync(0xffffffffu, sup)) {
                if (lane == 0) {
                    s_pkj[npick] = j;
                    s_pbox[npick] = cb;
                    s_par[npick] = aj;
                    s_plab[npick] = lbl;
                }
                __syncwarp();
                npick++;
            }
        }
        if (lane == 0) {
            for (; npick < NPOST; ++npick) s_pkj[npick] = 0;
        }
    }
    __syncthreads();

    // ---- Outputs [scores | labels | boxes] f32 ----
    if (tid < NPOST) {
        const int k = tid;
        int j = s_pkj[k];
        unsigned long long key = U.s.keys[j];
        float score = __uint_as_float((unsigned int)(key >> 32));
        int idx = (int)(~(unsigned int)key);
        int q = idx / NC, lbl = idx - q * NC;
        float4 b = bx4[q];
        float x1 = (b.x - 0.5f * b.z) * img_w;
        float y1 = (b.y - 0.5f * b.w) * img_h;
        float x2 = (b.x + 0.5f * b.z) * img_w;
        float y2 = (b.y + 0.5f * b.w) * img_h;

        out[(size_t)img * NPOST + k] = score;
        out[(size_t)BS * NPOST + (size_t)img * NPOST + k] = (float)lbl;
        float* ob = out + (size_t)2 * BS * NPOST + ((size_t)img * NPOST + k) * 4;
        ob[0] = x1; ob[1] = y1; ob[2] = x2; ob[3] = y2;
    }
}

extern "C" void kernel_launch(void* const* d_in, const int* in_sizes, int n_in,
                              void* d_out, int out_size) {
    const float* pred_logits  = (const float*)d_in[0];
    const float* pred_boxes   = (const float*)d_in[1];
    const float* target_sizes = (const float*)d_in[2];
    float* out = (float*)d_out;
    (void)in_sizes; (void)n_in; (void)out_size;
    cudaFuncSetAttribute((const void*)nms_post_kernel,
                         cudaFuncAttributeMaxDynamicSharedMemorySize,
                         NVEC * (int)sizeof(float));
    nms_post_kernel<<<BS, NTHREADS, NVEC * sizeof(float)>>>(
        pred_logits, pred_boxes, target_sizes, out);
}